// round 1
// baseline (speedup 1.0000x reference)
#include <cuda_runtime.h>
#include <cuda_bf16.h>
#include <cstdint>

// ---------------- scratch (device globals; no allocation allowed) ----------
#define MAXN 50176  // padded 50000
__device__ float g_agg[MAXN * 128];
__device__ float g_t  [MAXN * 128];
__device__ float g_h  [MAXN * 128];
__device__ float g_pool[256 * 128];
__device__ float g_cnt [256];

// ---------------- zero ------------------------------------------------------
__global__ void zero_kernel(float* __restrict__ p, int n4) {
    int i = blockIdx.x * blockDim.x + threadIdx.x;
    if (i < n4) ((float4*)p)[i] = make_float4(0.f, 0.f, 0.f, 0.f);
}

// ---------------- edge scatter-add: agg[dst] += X[src] ----------------------
// one warp per edge; lane handles 4 channels via float4 + red.global.add.v4
__global__ void scatter_kernel(const float* __restrict__ X,
                               const int* __restrict__ src,
                               const int* __restrict__ dst,
                               float* __restrict__ agg, int E) {
    int warp = (blockIdx.x * blockDim.x + threadIdx.x) >> 5;
    int lane = threadIdx.x & 31;
    if (warp >= E) return;
    int s = __ldg(src + warp);
    int d = __ldg(dst + warp);
    float4 v = __ldg(((const float4*)(X + (size_t)s * 128)) + lane);
    float* p = agg + (size_t)d * 128 + lane * 4;
    asm volatile("red.global.add.v4.f32 [%0], {%1, %2, %3, %4};"
                 :: "l"(p), "f"(v.x), "f"(v.y), "f"(v.z), "f"(v.w) : "memory");
}

// ---------------- fused SGEMM: C = act((A [+Aadd]) @ W + bias) --------------
// A:[M,128], W:[128,128] row-major, C:[M,128]. Tile 128x128, 256 thr, 8x8/thr.
__global__ __launch_bounds__(256, 2)
void gemm128_kernel(const float* __restrict__ A, const float* __restrict__ Aadd,
                    const float* __restrict__ W, const float* __restrict__ bias,
                    float* __restrict__ C, int M, int do_relu) {
    __shared__ float As[128][32];
    __shared__ float Ws[32][128];
    const int tid  = threadIdx.x;
    const int row0 = blockIdx.x * 128;
    const int tx = tid & 15, ty = tid >> 4;
    const int rrow = ty * 8, ccol = tx * 8;

    float acc[8][8];
#pragma unroll
    for (int i = 0; i < 8; i++)
#pragma unroll
        for (int j = 0; j < 8; j++) acc[i][j] = 0.f;

    for (int k0 = 0; k0 < 128; k0 += 32) {
        // stage A subtile [128 x 32]
#pragma unroll
        for (int t = 0; t < 4; t++) {
            int idx = tid + t * 256;        // 0..1023 float4s
            int r  = idx >> 3;              // 0..127
            int c4 = idx & 7;               // 0..7
            int grow = row0 + r;
            float4 v = make_float4(0.f, 0.f, 0.f, 0.f);
            if (grow < M) {
                v = __ldg(((const float4*)(A + (size_t)grow * 128 + k0)) + c4);
                if (Aadd) {
                    float4 u = __ldg(((const float4*)(Aadd + (size_t)grow * 128 + k0)) + c4);
                    v.x += u.x; v.y += u.y; v.z += u.z; v.w += u.w;
                }
            }
            *(float4*)&As[r][c4 * 4] = v;
        }
        // stage W subtile [32 x 128]
#pragma unroll
        for (int t = 0; t < 4; t++) {
            int idx = tid + t * 256;
            int r  = idx >> 5;              // 0..31
            int c4 = idx & 31;              // 0..31
            float4 v = __ldg(((const float4*)(W + (size_t)(k0 + r) * 128)) + c4);
            *(float4*)&Ws[r][c4 * 4] = v;
        }
        __syncthreads();

#pragma unroll 8
        for (int k = 0; k < 32; k++) {
            float a[8], b[8];
#pragma unroll
            for (int i = 0; i < 8; i++) a[i] = As[rrow + i][k];
            float4 b0 = *(float4*)&Ws[k][ccol];
            float4 b1 = *(float4*)&Ws[k][ccol + 4];
            b[0] = b0.x; b[1] = b0.y; b[2] = b0.z; b[3] = b0.w;
            b[4] = b1.x; b[5] = b1.y; b[6] = b1.z; b[7] = b1.w;
#pragma unroll
            for (int i = 0; i < 8; i++)
#pragma unroll
                for (int j = 0; j < 8; j++)
                    acc[i][j] += a[i] * b[j];
        }
        __syncthreads();
    }

    // epilogue: bias + optional relu
    float4 bv0 = __ldg((const float4*)(bias + ccol));
    float4 bv1 = __ldg((const float4*)(bias + ccol + 4));
    float bb[8] = {bv0.x, bv0.y, bv0.z, bv0.w, bv1.x, bv1.y, bv1.z, bv1.w};
#pragma unroll
    for (int i = 0; i < 8; i++) {
        int grow = row0 + rrow + i;
        if (grow < M) {
            float o[8];
#pragma unroll
            for (int j = 0; j < 8; j++) {
                o[j] = acc[i][j] + bb[j];
                if (do_relu) o[j] = fmaxf(o[j], 0.f);
            }
            *(float4*)(C + (size_t)grow * 128 + ccol)     = make_float4(o[0], o[1], o[2], o[3]);
            *(float4*)(C + (size_t)grow * 128 + ccol + 4) = make_float4(o[4], o[5], o[6], o[7]);
        }
    }
}

// ---------------- mean-pool accumulate --------------------------------------
__global__ void pool_kernel(const float* __restrict__ H, const int* __restrict__ batch,
                            float* __restrict__ sums, float* __restrict__ cnt, int N) {
    int node = (blockIdx.x * blockDim.x + threadIdx.x) >> 5;
    int lane = threadIdx.x & 31;
    if (node >= N) return;
    int g = __ldg(batch + node);
    float4 v = __ldg(((const float4*)(H + (size_t)node * 128)) + lane);
    float* p = sums + (size_t)g * 128 + lane * 4;
    asm volatile("red.global.add.v4.f32 [%0], {%1, %2, %3, %4};"
                 :: "l"(p), "f"(v.x), "f"(v.y), "f"(v.z), "f"(v.w) : "memory");
    if (lane == 0)
        atomicAdd(cnt + g, 1.0f);
}

// ---------------- head: out = (sums/cnt) @ Wl + bl --------------------------
__global__ void final_kernel(const float* __restrict__ sums, const float* __restrict__ cnt,
                             const float* __restrict__ Wl, const float* __restrict__ bl,
                             float* __restrict__ out) {
    int g = blockIdx.x;
    int o = threadIdx.x;  // 64 threads
    __shared__ float p[128];
    float c = fmaxf(__ldg(cnt + g), 1.0f);
    for (int k = threadIdx.x; k < 128; k += 64)
        p[k] = __ldg(sums + g * 128 + k) / c;
    __syncthreads();
    float acc = __ldg(bl + o);
#pragma unroll 16
    for (int k = 0; k < 128; k++)
        acc += p[k] * __ldg(Wl + k * 64 + o);
    out[g * 64 + o] = acc;
}

// ---------------- launch -----------------------------------------------------
extern "C" void kernel_launch(void* const* d_in, const int* in_sizes, int n_in,
                              void* d_out, int out_size) {
    const float* x     = (const float*)d_in[0];
    const int*   ei    = (const int*)  d_in[1];
    const int*   batch = (const int*)  d_in[2];
    const float* W1a = (const float*)d_in[3];
    const float* b1a = (const float*)d_in[4];
    const float* W1b = (const float*)d_in[5];
    const float* b1b = (const float*)d_in[6];
    const float* W2a = (const float*)d_in[7];
    const float* b2a = (const float*)d_in[8];
    const float* W2b = (const float*)d_in[9];
    const float* b2b = (const float*)d_in[10];
    const float* Wl  = (const float*)d_in[11];
    const float* bl  = (const float*)d_in[12];
    float* out = (float*)d_out;

    const int N = in_sizes[0] / 128;
    const int E = in_sizes[1] / 2;
    const int* src = ei;
    const int* dst = ei + E;

    float *agg, *t, *h, *pool, *cnt;
    cudaGetSymbolAddress((void**)&agg,  g_agg);
    cudaGetSymbolAddress((void**)&t,    g_t);
    cudaGetSymbolAddress((void**)&h,    g_h);
    cudaGetSymbolAddress((void**)&pool, g_pool);
    cudaGetSymbolAddress((void**)&cnt,  g_cnt);

    const int n4       = N * 32;                    // float4 count of node tensor
    const int zblocks  = (n4 + 255) / 256;
    const int eblocks  = (E + 7) / 8;               // 8 warps/block, 1 warp/edge
    const int gblocks  = (N + 127) / 128;
    const int pblocks  = (N + 7) / 8;

    // ---- layer 1 ----
    zero_kernel   <<<zblocks, 256>>>(agg, n4);
    scatter_kernel<<<eblocks, 256>>>(x, src, dst, agg, E);
    gemm128_kernel<<<gblocks, 256>>>(x, agg, W1a, b1a, t, N, 1);
    gemm128_kernel<<<gblocks, 256>>>(t, nullptr, W1b, b1b, h, N, 0);

    // ---- layer 2 ----
    zero_kernel   <<<zblocks, 256>>>(agg, n4);
    scatter_kernel<<<eblocks, 256>>>(h, src, dst, agg, E);
    gemm128_kernel<<<gblocks, 256>>>(h, agg, W2a, b2a, t, N, 1);
    gemm128_kernel<<<gblocks, 256>>>(t, nullptr, W2b, b2b, h, N, 0);

    // ---- pool + head ----
    zero_kernel <<<32, 256>>>(pool, 256 * 128 / 4);
    zero_kernel <<<1,  64>>>(cnt, 64);
    pool_kernel <<<pblocks, 256>>>(h, batch, pool, cnt, N);
    final_kernel<<<256, 64>>>(pool, cnt, Wl, bl, out);
}

// round 2
// speedup vs baseline: 1.1046x; 1.1046x over previous
#include <cuda_runtime.h>
#include <cuda_bf16.h>
#include <cstdint>

// ---------------- scratch (device globals; no allocation allowed) ----------
#define MAXN 50176  // padded 50000 (multiple of 128)
__device__ float g_agg[MAXN * 128];
__device__ float g_t  [MAXN * 128];
__device__ float g_h  [MAXN * 128];
__device__ float g_pool[256 * 128];
__device__ float g_cnt [256];

// ---------------- zero / copy ----------------------------------------------
__global__ void zero_kernel(float* __restrict__ p, int n4) {
    int i = blockIdx.x * blockDim.x + threadIdx.x;
    if (i < n4) ((float4*)p)[i] = make_float4(0.f, 0.f, 0.f, 0.f);
}

__global__ void copy_kernel(const float* __restrict__ s, float* __restrict__ d, int n4) {
    int i = blockIdx.x * blockDim.x + threadIdx.x;
    if (i < n4) ((float4*)d)[i] = ((const float4*)s)[i];
}

// ---------------- edge scatter-add: agg[dst] += X[src] ----------------------
__global__ void scatter_kernel(const float* __restrict__ X,
                               const int* __restrict__ src,
                               const int* __restrict__ dst,
                               float* __restrict__ agg, int E) {
    int warp = (blockIdx.x * blockDim.x + threadIdx.x) >> 5;
    int lane = threadIdx.x & 31;
    if (warp >= E) return;
    int s = __ldg(src + warp);
    int d = __ldg(dst + warp);
    float4 v = __ldg(((const float4*)(X + (size_t)s * 128)) + lane);
    float* p = agg + (size_t)d * 128 + lane * 4;
    asm volatile("red.global.add.v4.f32 [%0], {%1, %2, %3, %4};"
                 :: "l"(p), "f"(v.x), "f"(v.y), "f"(v.z), "f"(v.w) : "memory");
}

// ---------------- SGEMM via packed f32x2: C = act(A @ W + bias) -------------
// A:[M(pad),128], W:[128,128] row-major, C:[M,128].
// 128x128 CTA tile, 256 thr, 8x8 per thread, cp.async double-buffered TK=16.
#define TK 16

__global__ __launch_bounds__(256, 2)
void gemm128_kernel(const float* __restrict__ A, const float* __restrict__ W,
                    const float* __restrict__ bias, float* __restrict__ C,
                    int M, int do_relu) {
    __shared__ float As[2][128][TK];
    __shared__ float Ws[2][TK][128];
    const int tid  = threadIdx.x;
    const int row0 = blockIdx.x * 128;
    const int tx = tid & 15, ty = tid >> 4;
    const int rrow = ty * 8, ccol = tx * 8;

    unsigned long long acc[8][4];
#pragma unroll
    for (int i = 0; i < 8; i++)
#pragma unroll
        for (int j = 0; j < 4; j++) acc[i][j] = 0ull;

    // -- staging: 128xTK A chunk (512 x 16B) + TKx128 W chunk (512 x 16B)
#define STAGE(K0, BUF) do {                                                     \
        _Pragma("unroll")                                                       \
        for (int t = 0; t < 2; t++) {                                           \
            int ch = tid + t * 256;                                             \
            int r = ch >> 2, c = ch & 3;                                        \
            const float* g = A + (size_t)(row0 + r) * 128 + (K0) + c * 4;       \
            unsigned sm = (unsigned)__cvta_generic_to_shared(&As[BUF][r][c*4]); \
            asm volatile("cp.async.cg.shared.global [%0], [%1], 16;"            \
                         :: "r"(sm), "l"(g));                                   \
        }                                                                       \
        _Pragma("unroll")                                                       \
        for (int t = 0; t < 2; t++) {                                           \
            int ch = tid + t * 256;                                             \
            int r = ch >> 5, c = ch & 31;                                       \
            const float* g = W + (size_t)((K0) + r) * 128 + c * 4;              \
            unsigned sm = (unsigned)__cvta_generic_to_shared(&Ws[BUF][r][c*4]); \
            asm volatile("cp.async.cg.shared.global [%0], [%1], 16;"            \
                         :: "r"(sm), "l"(g));                                   \
        }                                                                       \
        asm volatile("cp.async.commit_group;");                                 \
    } while (0)

    STAGE(0, 0);

    for (int s = 0; s < 128 / TK; s++) {
        if (s < 128 / TK - 1) {
            STAGE((s + 1) * TK, (s + 1) & 1);
            asm volatile("cp.async.wait_group 1;");
        } else {
            asm volatile("cp.async.wait_group 0;");
        }
        __syncthreads();

        const int b = s & 1;
#pragma unroll
        for (int k4 = 0; k4 < TK / 4; k4++) {
            float4 av[8];
#pragma unroll
            for (int i = 0; i < 8; i++)
                av[i] = *(const float4*)&As[b][rrow + i][k4 * 4];
#pragma unroll
            for (int kk = 0; kk < 4; kk++) {
                int k = k4 * 4 + kk;
                ulonglong2 w01 = *(const ulonglong2*)&Ws[b][k][ccol];
                ulonglong2 w23 = *(const ulonglong2*)&Ws[b][k][ccol + 4];
#pragma unroll
                for (int i = 0; i < 8; i++) {
                    float a = (kk == 0) ? av[i].x : (kk == 1) ? av[i].y
                            : (kk == 2) ? av[i].z : av[i].w;
                    unsigned long long a2;
                    asm("mov.b64 %0, {%1, %1};" : "=l"(a2) : "f"(a));
                    asm("fma.rn.f32x2 %0, %1, %2, %0;"
                        : "+l"(acc[i][0]) : "l"(a2), "l"(w01.x));
                    asm("fma.rn.f32x2 %0, %1, %2, %0;"
                        : "+l"(acc[i][1]) : "l"(a2), "l"(w01.y));
                    asm("fma.rn.f32x2 %0, %1, %2, %0;"
                        : "+l"(acc[i][2]) : "l"(a2), "l"(w23.x));
                    asm("fma.rn.f32x2 %0, %1, %2, %0;"
                        : "+l"(acc[i][3]) : "l"(a2), "l"(w23.y));
                }
            }
        }
        __syncthreads();
    }

    // epilogue: unpack + bias + optional relu
    float4 bv0 = __ldg((const float4*)(bias + ccol));
    float4 bv1 = __ldg((const float4*)(bias + ccol + 4));
    float bb[8] = {bv0.x, bv0.y, bv0.z, bv0.w, bv1.x, bv1.y, bv1.z, bv1.w};
#pragma unroll
    for (int i = 0; i < 8; i++) {
        int grow = row0 + rrow + i;
        if (grow < M) {
            float o[8];
#pragma unroll
            for (int j = 0; j < 4; j++) {
                float lo, hi;
                asm("mov.b64 {%0, %1}, %2;" : "=f"(lo), "=f"(hi) : "l"(acc[i][j]));
                o[2 * j]     = lo + bb[2 * j];
                o[2 * j + 1] = hi + bb[2 * j + 1];
            }
            if (do_relu)
#pragma unroll
                for (int j = 0; j < 8; j++) o[j] = fmaxf(o[j], 0.f);
            *(float4*)(C + (size_t)grow * 128 + ccol)     = make_float4(o[0], o[1], o[2], o[3]);
            *(float4*)(C + (size_t)grow * 128 + ccol + 4) = make_float4(o[4], o[5], o[6], o[7]);
        }
    }
}

// ---------------- mean-pool accumulate --------------------------------------
__global__ void pool_kernel(const float* __restrict__ H, const int* __restrict__ batch,
                            float* __restrict__ sums, float* __restrict__ cnt, int N) {
    int node = (blockIdx.x * blockDim.x + threadIdx.x) >> 5;
    int lane = threadIdx.x & 31;
    if (node >= N) return;
    int g = __ldg(batch + node);
    float4 v = __ldg(((const float4*)(H + (size_t)node * 128)) + lane);
    float* p = sums + (size_t)g * 128 + lane * 4;
    asm volatile("red.global.add.v4.f32 [%0], {%1, %2, %3, %4};"
                 :: "l"(p), "f"(v.x), "f"(v.y), "f"(v.z), "f"(v.w) : "memory");
    if (lane == 0)
        atomicAdd(cnt + g, 1.0f);
}

// ---------------- head: out = (sums/cnt) @ Wl + bl --------------------------
__global__ void final_kernel(const float* __restrict__ sums, const float* __restrict__ cnt,
                             const float* __restrict__ Wl, const float* __restrict__ bl,
                             float* __restrict__ out) {
    int g = blockIdx.x;
    int o = threadIdx.x;  // 64 threads
    __shared__ float p[128];
    float c = fmaxf(__ldg(cnt + g), 1.0f);
    for (int k = threadIdx.x; k < 128; k += 64)
        p[k] = __ldg(sums + g * 128 + k) / c;
    __syncthreads();
    float acc = __ldg(bl + o);
#pragma unroll 16
    for (int k = 0; k < 128; k++)
        acc += p[k] * __ldg(Wl + k * 64 + o);
    out[g * 64 + o] = acc;
}

// ---------------- launch -----------------------------------------------------
extern "C" void kernel_launch(void* const* d_in, const int* in_sizes, int n_in,
                              void* d_out, int out_size) {
    const float* x     = (const float*)d_in[0];
    const int*   ei    = (const int*)  d_in[1];
    const int*   batch = (const int*)  d_in[2];
    const float* W1a = (const float*)d_in[3];
    const float* b1a = (const float*)d_in[4];
    const float* W1b = (const float*)d_in[5];
    const float* b1b = (const float*)d_in[6];
    const float* W2a = (const float*)d_in[7];
    const float* b2a = (const float*)d_in[8];
    const float* W2b = (const float*)d_in[9];
    const float* b2b = (const float*)d_in[10];
    const float* Wl  = (const float*)d_in[11];
    const float* bl  = (const float*)d_in[12];
    float* out = (float*)d_out;

    const int N = in_sizes[0] / 128;
    const int E = in_sizes[1] / 2;
    const int* src = ei;
    const int* dst = ei + E;

    float *agg, *t, *h, *pool, *cnt;
    cudaGetSymbolAddress((void**)&agg,  g_agg);
    cudaGetSymbolAddress((void**)&t,    g_t);
    cudaGetSymbolAddress((void**)&h,    g_h);
    cudaGetSymbolAddress((void**)&pool, g_pool);
    cudaGetSymbolAddress((void**)&cnt,  g_cnt);

    const int n4      = N * 32;                 // float4 count of node tensor
    const int cblocks = (n4 + 255) / 256;
    const int eblocks = (E + 7) / 8;            // 1 warp per edge
    const int gblocks = (N + 127) / 128;
    const int pblocks = (N + 7) / 8;

    // ---- layer 1: agg = x; agg += sum_j x_j; MLP ----
    copy_kernel   <<<cblocks, 256>>>(x, agg, n4);
    scatter_kernel<<<eblocks, 256>>>(x, src, dst, agg, E);
    gemm128_kernel<<<gblocks, 256>>>(agg, W1a, b1a, t, N, 1);
    gemm128_kernel<<<gblocks, 256>>>(t,   W1b, b1b, h, N, 0);

    // ---- layer 2 ----
    copy_kernel   <<<cblocks, 256>>>(h, agg, n4);
    scatter_kernel<<<eblocks, 256>>>(h, src, dst, agg, E);
    gemm128_kernel<<<gblocks, 256>>>(agg, W2a, b2a, t, N, 1);
    gemm128_kernel<<<gblocks, 256>>>(t,   W2b, b2b, h, N, 0);

    // ---- pool + head ----
    zero_kernel <<<32, 256>>>(pool, 256 * 128 / 4);
    zero_kernel <<<1,  64>>>(cnt, 64);
    pool_kernel <<<pblocks, 256>>>(h, batch, pool, cnt, N);
    final_kernel<<<256, 64>>>(pool, cnt, Wl, bl, out);
}